// round 1
// baseline (speedup 1.0000x reference)
#include <cuda_runtime.h>
#include <cstdint>

#define BB    2
#define TDEC  2048
#define TENC  2048
#define DMOD  1024
#define NH    16
#define DH    64
#define MROWS (BB * TDEC)   // 4096

// Scratch (allocation-free rule: __device__ globals)
__device__ float g_Q[(size_t)MROWS * DMOD];
__device__ float g_K[(size_t)BB * TENC * DMOD];
__device__ float g_V[(size_t)BB * TENC * DMOD];
__device__ float g_Y[(size_t)MROWS * DMOD];

// ---------------------------------------------------------------------------
// C[M,N] = A[M,K] @ W[K,N] + bias[N]
// 128x128 block tile, BK=8, 256 threads, 8x8 microtile with split fragments
// (rows ty*4 and 64+ty*4, cols tx*4 and 64+tx*4) for conflict-free LDS.128.
// M % 128 == 0, N % 128 == 0, K % 8 == 0 assumed (true for all calls).
// ---------------------------------------------------------------------------
__global__ __launch_bounds__(256) void sgemm_bias_kernel(
    const float* __restrict__ A, const float* __restrict__ W,
    const float* __restrict__ bias, float* __restrict__ C,
    int M, int N, int K)
{
    __shared__ float As[8][128];
    __shared__ float Bs[8][128];

    const int tid  = threadIdx.x;
    const int brow = blockIdx.y * 128;
    const int bcol = blockIdx.x * 128;

    const int a_row = tid >> 1;            // 0..127
    const int a_k4  = (tid & 1) * 4;       // 0 or 4
    const int b_k   = tid >> 5;            // 0..7
    const int b_c4  = (tid & 31) * 4;      // 0..124

    const int ty = tid >> 4;               // 0..15
    const int tx = tid & 15;               // 0..15

    float acc[8][8];
#pragma unroll
    for (int i = 0; i < 8; i++)
#pragma unroll
        for (int j = 0; j < 8; j++) acc[i][j] = 0.f;

    const float* Aptr = A + (size_t)(brow + a_row) * K + a_k4;
    const float* Wptr = W + (size_t)b_k * N + bcol + b_c4;

    for (int k0 = 0; k0 < K; k0 += 8) {
        float4 av = *(const float4*)(Aptr + k0);
        float4 bv = *(const float4*)(Wptr + (size_t)k0 * N);
        As[a_k4 + 0][a_row] = av.x;
        As[a_k4 + 1][a_row] = av.y;
        As[a_k4 + 2][a_row] = av.z;
        As[a_k4 + 3][a_row] = av.w;
        *(float4*)&Bs[b_k][b_c4] = bv;
        __syncthreads();

#pragma unroll
        for (int k = 0; k < 8; k++) {
            float ar[8], br[8];
            *(float4*)&ar[0] = *(const float4*)&As[k][ty * 4];
            *(float4*)&ar[4] = *(const float4*)&As[k][64 + ty * 4];
            *(float4*)&br[0] = *(const float4*)&Bs[k][tx * 4];
            *(float4*)&br[4] = *(const float4*)&Bs[k][64 + tx * 4];
#pragma unroll
            for (int i = 0; i < 8; i++)
#pragma unroll
                for (int j = 0; j < 8; j++)
                    acc[i][j] += ar[i] * br[j];
        }
        __syncthreads();
    }

    float bc0[4], bc1[4];
    *(float4*)&bc0[0] = *(const float4*)&bias[bcol + tx * 4];
    *(float4*)&bc1[0] = *(const float4*)&bias[bcol + 64 + tx * 4];

#pragma unroll
    for (int i = 0; i < 8; i++) {
        int row = brow + ((i < 4) ? (ty * 4 + i) : (64 + ty * 4 + (i - 4)));
        float4 o0, o1;
        o0.x = acc[i][0] + bc0[0];
        o0.y = acc[i][1] + bc0[1];
        o0.z = acc[i][2] + bc0[2];
        o0.w = acc[i][3] + bc0[3];
        o1.x = acc[i][4] + bc1[0];
        o1.y = acc[i][5] + bc1[1];
        o1.z = acc[i][6] + bc1[2];
        o1.w = acc[i][7] + bc1[3];
        *(float4*)&C[(size_t)row * N + bcol + tx * 4]      = o0;
        *(float4*)&C[(size_t)row * N + bcol + 64 + tx * 4] = o1;
    }
}

// ---------------------------------------------------------------------------
// Flash attention over split heads.
// Block = (q-tile of 64 rows, head, batch); 64 threads, one thread per query
// row. Q row (64 floats) + O accumulator (64 floats) + score tile (64 floats)
// live in registers; K/V tiles staged in shared, read as warp-wide broadcasts
// (all lanes same address -> conflict-free).
// ---------------------------------------------------------------------------
__global__ __launch_bounds__(64) void attn_kernel()
{
    const int t  = threadIdx.x;        // 0..63, query row within tile
    const int qt = blockIdx.x;         // 0..31
    const int h  = blockIdx.y;         // 0..15
    const int b  = blockIdx.z;         // 0..1
    const int q  = qt * 64 + t;

    __shared__ float4 Ks[64][16];
    __shared__ float4 Vs[64][16];

    const float scale = 0.125f;        // 1/sqrt(64)

    float4 Qr[16];
    {
        const float4* qptr = (const float4*)(g_Q + ((size_t)b * TDEC + q) * DMOD + h * DH);
#pragma unroll
        for (int i = 0; i < 16; i++) {
            float4 v = qptr[i];
            v.x *= scale; v.y *= scale; v.z *= scale; v.w *= scale;
            Qr[i] = v;
        }
    }

    float m = -1e30f, l = 0.f;
    float4 Ob[16];
#pragma unroll
    for (int i = 0; i < 16; i++) Ob[i] = make_float4(0.f, 0.f, 0.f, 0.f);

    const float4* kbase = (const float4*)(g_K + (size_t)b * TENC * DMOD + h * DH);
    const float4* vbase = (const float4*)(g_V + (size_t)b * TENC * DMOD + h * DH);
    const int row_f4 = DMOD / 4;       // 256 float4 per token row

    for (int kt = 0; kt < TENC / 64; kt++) {
        __syncthreads();
        const float4* k4 = kbase + (size_t)kt * 64 * row_f4;
        const float4* v4 = vbase + (size_t)kt * 64 * row_f4;
#pragma unroll
        for (int i = 0; i < 16; i++) {
            int idx = i * 64 + t;      // 0..1023
            int row = idx >> 4;
            int c   = idx & 15;
            Ks[row][c] = k4[(size_t)row * row_f4 + c];
            Vs[row][c] = v4[(size_t)row * row_f4 + c];
        }
        __syncthreads();

        // scores s[j] = (Q/8) . K_j
        float s[64];
#pragma unroll 8
        for (int j = 0; j < 64; j++) {
            float acc = 0.f;
#pragma unroll
            for (int d = 0; d < 16; d++) {
                float4 kv = Ks[j][d];
                acc += Qr[d].x * kv.x + Qr[d].y * kv.y
                     + Qr[d].z * kv.z + Qr[d].w * kv.w;
            }
            s[j] = acc;
        }

        // online softmax
        float tmax = m;
#pragma unroll
        for (int j = 0; j < 64; j++) tmax = fmaxf(tmax, s[j]);
        float corr = __expf(m - tmax);
        m = tmax;
        float lsum = 0.f;
#pragma unroll
        for (int j = 0; j < 64; j++) {
            float p = __expf(s[j] - m);
            s[j] = p;
            lsum += p;
        }
        l = l * corr + lsum;

#pragma unroll
        for (int i = 0; i < 16; i++) {
            Ob[i].x *= corr; Ob[i].y *= corr; Ob[i].z *= corr; Ob[i].w *= corr;
        }
#pragma unroll 8
        for (int j = 0; j < 64; j++) {
            float p = s[j];
#pragma unroll
            for (int d = 0; d < 16; d++) {
                float4 vv = Vs[j][d];
                Ob[d].x += p * vv.x;
                Ob[d].y += p * vv.y;
                Ob[d].z += p * vv.z;
                Ob[d].w += p * vv.w;
            }
        }
    }

    float inv = 1.f / l;
    float4* yptr = (float4*)(g_Y + ((size_t)b * TDEC + q) * DMOD + h * DH);
#pragma unroll
    for (int i = 0; i < 16; i++) {
        float4 o = Ob[i];
        o.x *= inv; o.y *= inv; o.z *= inv; o.w *= inv;
        yptr[i] = o;
    }
}

// ---------------------------------------------------------------------------
extern "C" void kernel_launch(void* const* d_in, const int* in_sizes, int n_in,
                              void* d_out, int out_size)
{
    (void)in_sizes; (void)n_in; (void)out_size;

    const float* tgt    = (const float*)d_in[0];
    const float* memory = (const float*)d_in[1];
    const float* W_q    = (const float*)d_in[2];
    const float* b_q    = (const float*)d_in[3];
    const float* W_k    = (const float*)d_in[4];
    const float* b_k    = (const float*)d_in[5];
    const float* W_v    = (const float*)d_in[6];
    const float* b_v    = (const float*)d_in[7];
    const float* W_o    = (const float*)d_in[8];
    const float* b_o    = (const float*)d_in[9];
    float* out = (float*)d_out;

    float *pQ, *pK, *pV, *pY;
    cudaGetSymbolAddress((void**)&pQ, g_Q);
    cudaGetSymbolAddress((void**)&pK, g_K);
    cudaGetSymbolAddress((void**)&pV, g_V);
    cudaGetSymbolAddress((void**)&pY, g_Y);

    dim3 gblk(256);
    dim3 ggrid(DMOD / 128, MROWS / 128);   // (8, 32)

    // Projections
    sgemm_bias_kernel<<<ggrid, gblk>>>(tgt,    W_q, b_q, pQ, MROWS, DMOD, DMOD);
    sgemm_bias_kernel<<<ggrid, gblk>>>(memory, W_k, b_k, pK, MROWS, DMOD, DMOD);
    sgemm_bias_kernel<<<ggrid, gblk>>>(memory, W_v, b_v, pV, MROWS, DMOD, DMOD);

    // Attention
    dim3 agrid(TDEC / 64, NH, BB);         // (32, 16, 2)
    attn_kernel<<<agrid, 64>>>();

    // Output projection
    sgemm_bias_kernel<<<ggrid, gblk>>>(pY, W_o, b_o, out, MROWS, DMOD, DMOD);
}

// round 4
// speedup vs baseline: 2.8838x; 2.8838x over previous
#include <cuda_runtime.h>
#include <cuda_bf16.h>
#include <cstdint>

#define BB    2
#define TDEC  2048
#define TENC  2048
#define DMOD  1024
#define NH    16
#define DH    64
#define MROWS (BB * TDEC)   // 4096

// ---------------------------------------------------------------------------
// Scratch (allocation-free rule: __device__ globals)
// ---------------------------------------------------------------------------
__device__ float g_Q[(size_t)MROWS * DMOD];
__device__ float g_K[(size_t)MROWS * DMOD];
__device__ float g_V[(size_t)MROWS * DMOD];
__device__ float g_Y[(size_t)MROWS * DMOD];

// bf16 hi/lo splits
__device__ __nv_bfloat16 g_a1_hi[(size_t)MROWS * DMOD];
__device__ __nv_bfloat16 g_a1_lo[(size_t)MROWS * DMOD];
__device__ __nv_bfloat16 g_a2_hi[(size_t)MROWS * DMOD];
__device__ __nv_bfloat16 g_a2_lo[(size_t)MROWS * DMOD];
__device__ __nv_bfloat16 g_wq_hi[(size_t)DMOD * DMOD];
__device__ __nv_bfloat16 g_wq_lo[(size_t)DMOD * DMOD];
__device__ __nv_bfloat16 g_wk_hi[(size_t)DMOD * DMOD];
__device__ __nv_bfloat16 g_wk_lo[(size_t)DMOD * DMOD];
__device__ __nv_bfloat16 g_wv_hi[(size_t)DMOD * DMOD];
__device__ __nv_bfloat16 g_wv_lo[(size_t)DMOD * DMOD];
__device__ __nv_bfloat16 g_wo_hi[(size_t)DMOD * DMOD];
__device__ __nv_bfloat16 g_wo_lo[(size_t)DMOD * DMOD];

// attention-layout tensors: Q/K [b][h][tok][d], Vt [b][h][d][tok]
__device__ __nv_bfloat16 g_qs_hi[(size_t)MROWS * DMOD];
__device__ __nv_bfloat16 g_qs_lo[(size_t)MROWS * DMOD];
__device__ __nv_bfloat16 g_ks_hi[(size_t)MROWS * DMOD];
__device__ __nv_bfloat16 g_ks_lo[(size_t)MROWS * DMOD];
__device__ __nv_bfloat16 g_vt_hi[(size_t)MROWS * DMOD];
__device__ __nv_bfloat16 g_vt_lo[(size_t)MROWS * DMOD];

// ---------------------------------------------------------------------------
// Helpers (sm_80-compatible PTX only — no tcgen05, harness targets compute_103)
// ---------------------------------------------------------------------------
__device__ __forceinline__ uint32_t smem_u32(const void* p) {
    uint32_t r;
    asm("{ .reg .u64 t; cvta.to.shared.u64 t, %1; cvt.u32.u64 %0, t; }"
        : "=r"(r) : "l"(p));
    return r;
}

__device__ __forceinline__ void cp16(uint32_t dst, const void* src) {
    asm volatile("cp.async.cg.shared.global [%0], [%1], 16;\n"
                 :: "r"(dst), "l"(src));
}
#define CP_COMMIT() asm volatile("cp.async.commit_group;\n" ::: "memory")
#define CP_WAIT0()  asm volatile("cp.async.wait_group 0;\n" ::: "memory")

// D += A(16x16 bf16, row) * B(16x8 bf16, col), fp32 accum
__device__ __forceinline__ void mma_bf16(float* d, const uint32_t* a, const uint32_t* b) {
    asm volatile(
        "mma.sync.aligned.m16n8k16.row.col.f32.bf16.bf16.f32 "
        "{%0,%1,%2,%3}, {%4,%5,%6,%7}, {%8,%9}, {%0,%1,%2,%3};\n"
        : "+f"(d[0]), "+f"(d[1]), "+f"(d[2]), "+f"(d[3])
        : "r"(a[0]), "r"(a[1]), "r"(a[2]), "r"(a[3]),
          "r"(b[0]), "r"(b[1]));
}

__device__ __forceinline__ uint32_t pack_bf16(float a, float b) {
    __nv_bfloat162 h(__float2bfloat16(a), __float2bfloat16(b));
    return *reinterpret_cast<uint32_t*>(&h);
}
__device__ __forceinline__ void split_pack2(float a, float b, uint32_t& hi, uint32_t& lo) {
    __nv_bfloat16 ha = __float2bfloat16(a), hb = __float2bfloat16(b);
    float la = a - __bfloat162float(ha);
    float lb = b - __bfloat162float(hb);
    __nv_bfloat162 H(ha, hb);
    __nv_bfloat162 L(__float2bfloat16(la), __float2bfloat16(lb));
    hi = *reinterpret_cast<uint32_t*>(&H);
    lo = *reinterpret_cast<uint32_t*>(&L);
}

// ---------------------------------------------------------------------------
// fp32 -> bf16 hi/lo (row-major, same layout)
// ---------------------------------------------------------------------------
__global__ __launch_bounds__(256) void conv_split_kernel(
    const float* __restrict__ x, __nv_bfloat16* __restrict__ hi,
    __nv_bfloat16* __restrict__ lo, int n4)
{
    int i = blockIdx.x * blockDim.x + threadIdx.x;
    if (i >= n4) return;
    float4 v = ((const float4*)x)[i];
    __nv_bfloat16 h0 = __float2bfloat16(v.x);
    __nv_bfloat16 h1 = __float2bfloat16(v.y);
    __nv_bfloat16 h2 = __float2bfloat16(v.z);
    __nv_bfloat16 h3 = __float2bfloat16(v.w);
    __nv_bfloat162* hp = (__nv_bfloat162*)(hi + (size_t)i * 4);
    __nv_bfloat162* lp = (__nv_bfloat162*)(lo + (size_t)i * 4);
    hp[0] = __nv_bfloat162(h0, h1);
    hp[1] = __nv_bfloat162(h2, h3);
    lp[0] = __nv_bfloat162(__float2bfloat16(v.x - __bfloat162float(h0)),
                           __float2bfloat16(v.y - __bfloat162float(h1)));
    lp[1] = __nv_bfloat162(__float2bfloat16(v.z - __bfloat162float(h2)),
                           __float2bfloat16(v.w - __bfloat162float(h3)));
}

// ---------------------------------------------------------------------------
// W (K x N, fp32) -> Wt_hi/Wt_lo (N x K, bf16) transpose + split
// ---------------------------------------------------------------------------
__global__ __launch_bounds__(256) void convT_split_kernel(
    const float* __restrict__ W, __nv_bfloat16* __restrict__ hiT,
    __nv_bfloat16* __restrict__ loT)
{
    __shared__ float tile[32][33];
    int tx = threadIdx.x, ty = threadIdx.y;      // 32 x 8
    int n0 = blockIdx.x * 32, k0 = blockIdx.y * 32;
#pragma unroll
    for (int r = 0; r < 4; r++)
        tile[ty + 8 * r][tx] = W[(size_t)(k0 + ty + 8 * r) * DMOD + n0 + tx];
    __syncthreads();
#pragma unroll
    for (int r = 0; r < 4; r++) {
        float v = tile[tx][ty + 8 * r];
        __nv_bfloat16 h = __float2bfloat16(v);
        size_t o = (size_t)(n0 + ty + 8 * r) * DMOD + k0 + tx;
        hiT[o] = h;
        loT[o] = __float2bfloat16(v - __bfloat162float(h));
    }
}

// ---------------------------------------------------------------------------
// [b,tok, h*64+d] fp32 -> [b][h][tok][d] bf16 hi/lo (optionally scaled)
// ---------------------------------------------------------------------------
__global__ __launch_bounds__(256) void qk_permute_split_kernel(
    const float* __restrict__ X, __nv_bfloat16* __restrict__ hi,
    __nv_bfloat16* __restrict__ lo, float scale)
{
    int i = blockIdx.x * 256 + threadIdx.x;       // float4 granule, 1,048,576 total
    int d4  = i & 15;
    int tok = (i >> 4) & 2047;
    int h   = (i >> 15) & 15;
    int b   = i >> 19;
    float4 v = *(const float4*)(X + (((size_t)b * TDEC + tok) * DMOD + h * DH + d4 * 4));
    v.x *= scale; v.y *= scale; v.z *= scale; v.w *= scale;
    __nv_bfloat16 h0 = __float2bfloat16(v.x);
    __nv_bfloat16 h1 = __float2bfloat16(v.y);
    __nv_bfloat16 h2 = __float2bfloat16(v.z);
    __nv_bfloat16 h3 = __float2bfloat16(v.w);
    size_t o = (size_t)i * 4;
    __nv_bfloat162* hp = (__nv_bfloat162*)(hi + o);
    __nv_bfloat162* lp = (__nv_bfloat162*)(lo + o);
    hp[0] = __nv_bfloat162(h0, h1);
    hp[1] = __nv_bfloat162(h2, h3);
    lp[0] = __nv_bfloat162(__float2bfloat16(v.x - __bfloat162float(h0)),
                           __float2bfloat16(v.y - __bfloat162float(h1)));
    lp[1] = __nv_bfloat162(__float2bfloat16(v.z - __bfloat162float(h2)),
                           __float2bfloat16(v.w - __bfloat162float(h3)));
}

// ---------------------------------------------------------------------------
// V [b,tok, h*64+d] fp32 -> Vt [b][h][d][tok] bf16 hi/lo
// ---------------------------------------------------------------------------
__global__ void v_transpose_split_kernel(
    const float* __restrict__ V, __nv_bfloat16* __restrict__ hi,
    __nv_bfloat16* __restrict__ lo)
{
    __shared__ float tile[32][33];
    int tx = threadIdx.x, ty = threadIdx.y;      // 32 x 8
    int t0 = blockIdx.x * 32;                    // tok tile
    int d0 = blockIdx.y * 32;                    // d tile
    int bh = blockIdx.z;                         // b*16+h
    int b = bh >> 4, h = bh & 15;
#pragma unroll
    for (int r = 0; r < 4; r++)
        tile[ty + 8 * r][tx] =
            V[((size_t)b * TENC + t0 + ty + 8 * r) * DMOD + h * DH + d0 + tx];
    __syncthreads();
#pragma unroll
    for (int r = 0; r < 4; r++) {
        float v = tile[tx][ty + 8 * r];          // [tokLocal=tx][dLocal=ty+8r]
        __nv_bfloat16 hv = __float2bfloat16(v);
        size_t o = ((size_t)bh * DH + d0 + ty + 8 * r) * TENC + t0 + tx;
        hi[o] = hv;
        lo[o] = __float2bfloat16(v - __bfloat162float(hv));
    }
}

// ---------------------------------------------------------------------------
// bf16x3 mma.sync GEMM: C[M,1024] = A[M,1024] @ Wt^T + bias
// CTA 128x128, 8 warps (2x4, warp tile 64x32), K chunk 32, cp.async 2-stage.
// smem: 2 buffers x 4 tiles (Ah, Al, Bh, Bl) x 2048 words (8KB), XOR swizzle.
// ---------------------------------------------------------------------------
#define SWZ(row, ch) (((ch) ^ (((row) >> 1) & 3)) << 2)

__global__ __launch_bounds__(256) void gemm_mma_kernel(
    const __nv_bfloat16* __restrict__ Ahi, const __nv_bfloat16* __restrict__ Alo,
    const __nv_bfloat16* __restrict__ Bhi, const __nv_bfloat16* __restrict__ Blo,
    const float* __restrict__ bias, float* __restrict__ C)
{
    extern __shared__ uint32_t sw[];
    uint32_t sbase = smem_u32(sw);
    const int tid = threadIdx.x;
    const int w = tid >> 5, lane = tid & 31, g = lane >> 2, t = lane & 3;
    const int wm = (w >> 2) * 64, wn = (w & 3) * 32;
    const int brow = blockIdx.y * 128, bcol = blockIdx.x * 128;

    float acc[4][4][4];
#pragma unroll
    for (int a = 0; a < 4; a++)
#pragma unroll
        for (int bq = 0; bq < 4; bq++)
#pragma unroll
            for (int cc = 0; cc < 4; cc++) acc[a][bq][cc] = 0.f;

    auto load_chunk = [&](int c, int bf) {
        const int k0 = c * 32;
#pragma unroll
        for (int i = 0; i < 8; i++) {
            int task = tid + i * 256;
            int tile = task >> 9;             // constant per i
            int r = (task >> 2) & 127;
            int ch = task & 3;
            const __nv_bfloat16* src;
            if (tile == 0)      src = Ahi + (size_t)(brow + r) * DMOD + k0 + ch * 8;
            else if (tile == 1) src = Alo + (size_t)(brow + r) * DMOD + k0 + ch * 8;
            else if (tile == 2) src = Bhi + (size_t)(bcol + r) * DMOD + k0 + ch * 8;
            else                src = Blo + (size_t)(bcol + r) * DMOD + k0 + ch * 8;
            uint32_t dst = sbase + (((bf * 4 + tile) * 2048) + r * 16 + SWZ(r, ch)) * 4;
            cp16(dst, src);
        }
        CP_COMMIT();
    };

    load_chunk(0, 0);
    for (int c = 0; c < 32; c++) {
        CP_WAIT0();
        __syncthreads();
        if (c + 1 < 32) load_chunk(c + 1, (c + 1) & 1);
        const uint32_t tb = (uint32_t)(c & 1) * 4 * 2048;

#pragma unroll
        for (int ks = 0; ks < 2; ks++) {
            uint32_t ah[4][4], al[4][4], bh2[4][2], bl2[4][2];
#pragma unroll
            for (int mt = 0; mt < 4; mt++) {
                int r0 = wm + mt * 16 + g, r1 = r0 + 8;
                ah[mt][0] = sw[tb + 0 * 2048 + r0 * 16 + SWZ(r0, ks * 2)     + t];
                ah[mt][1] = sw[tb + 0 * 2048 + r1 * 16 + SWZ(r1, ks * 2)     + t];
                ah[mt][2] = sw[tb + 0 * 2048 + r0 * 16 + SWZ(r0, ks * 2 + 1) + t];
                ah[mt][3] = sw[tb + 0 * 2048 + r1 * 16 + SWZ(r1, ks * 2 + 1) + t];
                al[mt][0] = sw[tb + 1 * 2048 + r0 * 16 + SWZ(r0, ks * 2)     + t];
                al[mt][1] = sw[tb + 1 * 2048 + r1 * 16 + SWZ(r1, ks * 2)     + t];
                al[mt][2] = sw[tb + 1 * 2048 + r0 * 16 + SWZ(r0, ks * 2 + 1) + t];
                al[mt][3] = sw[tb + 1 * 2048 + r1 * 16 + SWZ(r1, ks * 2 + 1) + t];
            }
#pragma unroll
            for (int nt = 0; nt < 4; nt++) {
                int r0 = wn + nt * 8 + g;
                bh2[nt][0] = sw[tb + 2 * 2048 + r0 * 16 + SWZ(r0, ks * 2)     + t];
                bh2[nt][1] = sw[tb + 2 * 2048 + r0 * 16 + SWZ(r0, ks * 2 + 1) + t];
                bl2[nt][0] = sw[tb + 3 * 2048 + r0 * 16 + SWZ(r0, ks * 2)     + t];
                bl2[nt][1] = sw[tb + 3 * 2048 + r0 * 16 + SWZ(r0, ks * 2 + 1) + t];
            }
#pragma unroll
            for (int mt = 0; mt < 4; mt++)
#pragma unroll
                for (int nt = 0; nt < 4; nt++) {
                    mma_bf16(acc[mt][nt], ah[mt], bh2[nt]);
                    mma_bf16(acc[mt][nt], al[mt], bh2[nt]);
                    mma_bf16(acc[mt][nt], ah[mt], bl2[nt]);
                }
        }
    }

#pragma unroll
    for (int mt = 0; mt < 4; mt++)
#pragma unroll
        for (int nt = 0; nt < 4; nt++) {
            int r0 = brow + wm + mt * 16 + g;
            int col = bcol + wn + nt * 8 + 2 * t;
            float b0 = bias[col], b1 = bias[col + 1];
            float2 v0 = make_float2(acc[mt][nt][0] + b0, acc[mt][nt][1] + b1);
            float2 v1 = make_float2(acc[mt][nt][2] + b0, acc[mt][nt][3] + b1);
            *(float2*)&C[(size_t)r0 * DMOD + col] = v0;
            *(float2*)&C[(size_t)(r0 + 8) * DMOD + col] = v1;
        }
}

// ---------------------------------------------------------------------------
// Flash attention on mma.sync (bf16x3 for QK and PV).
// Grid (TDEC/128, NH, BB); 8 warps; warp = 16 Q rows. K-tiles of 64 keys.
// smem: 2 buffers x 4 tiles (Kh, Kl, Vth, Vtl) x 2048 words, XOR swizzle.
// ---------------------------------------------------------------------------
#define ASWZ(row, ch) (((ch) ^ ((row) & 7)) << 2)

__global__ __launch_bounds__(256) void attn_mma_kernel(
    const __nv_bfloat16* __restrict__ Qh, const __nv_bfloat16* __restrict__ Ql,
    const __nv_bfloat16* __restrict__ Kh, const __nv_bfloat16* __restrict__ Kl,
    const __nv_bfloat16* __restrict__ Vh, const __nv_bfloat16* __restrict__ Vl)
{
    extern __shared__ uint32_t sw[];
    uint32_t sbase = smem_u32(sw);
    const int tid = threadIdx.x;
    const int w = tid >> 5, lane = tid & 31, g = lane >> 2, t = lane & 3;
    const int qb = blockIdx.x * 128;
    const int h = blockIdx.y, b = blockIdx.z;
    const size_t bh = (size_t)b * NH + h;

    // Q fragments (pre-scaled by 1/8 during prep), rows w*16 .. w*16+15
    uint32_t qh4[4][4], ql4[4][4];
    {
        const uint32_t* qH = (const uint32_t*)(Qh + (bh * TDEC + qb + w * 16) * DH);
        const uint32_t* qL = (const uint32_t*)(Ql + (bh * TDEC + qb + w * 16) * DH);
#pragma unroll
        for (int kt = 0; kt < 4; kt++) {
            qh4[kt][0] = qH[g * 32 + kt * 8 + t];
            qh4[kt][1] = qH[(g + 8) * 32 + kt * 8 + t];
            qh4[kt][2] = qH[g * 32 + kt * 8 + t + 4];
            qh4[kt][3] = qH[(g + 8) * 32 + kt * 8 + t + 4];
            ql4[kt][0] = qL[g * 32 + kt * 8 + t];
            ql4[kt][1] = qL[(g + 8) * 32 + kt * 8 + t];
            ql4[kt][2] = qL[g * 32 + kt * 8 + t + 4];
            ql4[kt][3] = qL[(g + 8) * 32 + kt * 8 + t + 4];
        }
    }

    float of[8][4];
#pragma unroll
    for (int nt = 0; nt < 8; nt++)
#pragma unroll
        for (int j = 0; j < 4; j++) of[nt][j] = 0.f;
    float m0 = -1e30f, m1 = -1e30f, l0 = 0.f, l1 = 0.f;

    auto load_kt = [&](int kt, int bf) {
#pragma unroll
        for (int i = 0; i < 8; i++) {
            int task = tid + i * 256;
            int tile = task >> 9;
            int r = (task >> 3) & 63;
            int ch = task & 7;
            const __nv_bfloat16* src;
            if (tile == 0)      src = Kh + (bh * TENC + kt * 64 + r) * DH + ch * 8;
            else if (tile == 1) src = Kl + (bh * TENC + kt * 64 + r) * DH + ch * 8;
            else if (tile == 2) src = Vh + (bh * DH + r) * TENC + kt * 64 + ch * 8;
            else                src = Vl + (bh * DH + r) * TENC + kt * 64 + ch * 8;
            uint32_t dst = sbase + (((bf * 4 + tile) * 2048) + r * 32 + ASWZ(r, ch)) * 4;
            cp16(dst, src);
        }
        CP_COMMIT();
    };

    load_kt(0, 0);
    for (int kt = 0; kt < 32; kt++) {
        CP_WAIT0();
        __syncthreads();
        if (kt + 1 < 32) load_kt(kt + 1, (kt + 1) & 1);
        const uint32_t tb = (uint32_t)(kt & 1) * 4 * 2048;

        // ---- S = Q K^T (3-term split) ----
        float sf[8][4];
#pragma unroll
        for (int nt = 0; nt < 8; nt++)
#pragma unroll
            for (int j = 0; j < 4; j++) sf[nt][j] = 0.f;

#pragma unroll
        for (int dk = 0; dk < 4; dk++) {
            uint32_t kb2[8][2], kl2[8][2];
#pragma unroll
            for (int nt = 0; nt < 8; nt++) {
                int r = nt * 8 + g;
                kb2[nt][0] = sw[tb + 0 * 2048 + r * 32 + ASWZ(r, dk * 2)     + t];
                kb2[nt][1] = sw[tb + 0 * 2048 + r * 32 + ASWZ(r, dk * 2 + 1) + t];
                kl2[nt][0] = sw[tb + 1 * 2048 + r * 32 + ASWZ(r, dk * 2)     + t];
                kl2[nt][1] = sw[tb + 1 * 2048 + r * 32 + ASWZ(r, dk * 2 + 1) + t];
            }
#pragma unroll
            for (int nt = 0; nt < 8; nt++) {
                mma_bf16(sf[nt], qh4[dk], kb2[nt]);
                mma_bf16(sf[nt], ql4[dk], kb2[nt]);
                mma_bf16(sf[nt], qh4[dk], kl2[nt]);
            }
        }

        // ---- online softmax (rows g and g+8) ----
        float mx0 = -1e30f, mx1 = -1e30f;
#pragma unroll
        for (int nt = 0; nt < 8; nt++) {
            mx0 = fmaxf(mx0, fmaxf(sf[nt][0], sf[nt][1]));
            mx1 = fmaxf(mx1, fmaxf(sf[nt][2], sf[nt][3]));
        }
        mx0 = fmaxf(mx0, __shfl_xor_sync(0xffffffffu, mx0, 1));
        mx0 = fmaxf(mx0, __shfl_xor_sync(0xffffffffu, mx0, 2));
        mx1 = fmaxf(mx1, __shfl_xor_sync(0xffffffffu, mx1, 1));
        mx1 = fmaxf(mx1, __shfl_xor_sync(0xffffffffu, mx1, 2));
        float mn0 = fmaxf(m0, mx0), mn1 = fmaxf(m1, mx1);
        float cr0 = __expf(m0 - mn0), cr1 = __expf(m1 - mn1);
        m0 = mn0; m1 = mn1;

        float s0 = 0.f, s1 = 0.f;
#pragma unroll
        for (int nt = 0; nt < 8; nt++) {
            sf[nt][0] = __expf(sf[nt][0] - mn0);
            sf[nt][1] = __expf(sf[nt][1] - mn0);
            sf[nt][2] = __expf(sf[nt][2] - mn1);
            sf[nt][3] = __expf(sf[nt][3] - mn1);
            s0 += sf[nt][0] + sf[nt][1];
            s1 += sf[nt][2] + sf[nt][3];
        }
        s0 += __shfl_xor_sync(0xffffffffu, s0, 1);
        s0 += __shfl_xor_sync(0xffffffffu, s0, 2);
        s1 += __shfl_xor_sync(0xffffffffu, s1, 1);
        s1 += __shfl_xor_sync(0xffffffffu, s1, 2);
        l0 = l0 * cr0 + s0;
        l1 = l1 * cr1 + s1;

#pragma unroll
        for (int nt = 0; nt < 8; nt++) {
            of[nt][0] *= cr0; of[nt][1] *= cr0;
            of[nt][2] *= cr1; of[nt][3] *= cr1;
        }

        // ---- pack P (C-frag -> A-frag, no shuffles), hi/lo split ----
        uint32_t ph[4][4], pl[4][4];
#pragma unroll
        for (int kk = 0; kk < 4; kk++) {
            split_pack2(sf[2 * kk][0],     sf[2 * kk][1],     ph[kk][0], pl[kk][0]);
            split_pack2(sf[2 * kk][2],     sf[2 * kk][3],     ph[kk][1], pl[kk][1]);
            split_pack2(sf[2 * kk + 1][0], sf[2 * kk + 1][1], ph[kk][2], pl[kk][2]);
            split_pack2(sf[2 * kk + 1][2], sf[2 * kk + 1][3], ph[kk][3], pl[kk][3]);
        }

        // ---- O += P V (3-term split) ----
#pragma unroll
        for (int kk = 0; kk < 4; kk++) {
            uint32_t vb2[8][2], vl2[8][2];
#pragma unroll
            for (int nt = 0; nt < 8; nt++) {
                int r = nt * 8 + g;                      // r = head-dim index
                vb2[nt][0] = sw[tb + 2 * 2048 + r * 32 + ASWZ(r, kk * 2)     + t];
                vb2[nt][1] = sw[tb + 2 * 2048 + r * 32 + ASWZ(r, kk * 2 + 1) + t];
                vl2[nt][0] = sw[tb + 3 * 2048 + r * 32 + ASWZ(r, kk * 2)     + t];
                vl2[nt][1] = sw[tb + 3 * 2048 + r * 32 + ASWZ(r, kk * 2 + 1) + t];
            }
#pragma unroll
            for (int nt = 0; nt < 8; nt++) {
                mma_bf16(of[nt], ph[kk], vb2[nt]);
                mma_bf16(of[nt], pl[kk], vb2[nt]);
                mma_bf16(of[nt], ph[kk], vl2[nt]);
            }
        }
    }

    // ---- epilogue: O /= l, write [b, tok, h*64+d] ----
    float i0 = 1.f / l0, i1 = 1.f / l1;
    int r0 = qb + w * 16 + g, r1 = r0 + 8;
#pragma unroll
    for (int nt = 0; nt < 8; nt++) {
        int col = h * DH + nt * 8 + 2 * t;
        float2 v0 = make_float2(of[nt][0] * i0, of[nt][1] * i0);
        float2 v1 = make_float2(of[nt][2] * i1, of[nt][3] * i1);
        *(float2*)&g_Y[((size_t)b * TDEC + r0) * DMOD + col] = v0;
        *(float2*)&g_Y[((size_t)b * TDEC + r1) * DMOD + col] = v1;
    }
}

// ---------------------------------------------------------------------------
extern "C" void kernel_launch(void* const* d_in, const int* in_sizes, int n_in,
                              void* d_out, int out_size)
{
    (void)in_sizes; (void)n_in; (void)out_size;

    const float* tgt    = (const float*)d_in[0];
    const float* memory = (const float*)d_in[1];
    const float* W_q    = (const float*)d_in[2];
    const float* b_q    = (const float*)d_in[3];
    const float* W_k    = (const float*)d_in[4];
    const float* b_k    = (const float*)d_in[5];
    const float* W_v    = (const float*)d_in[6];
    const float* b_v    = (const float*)d_in[7];
    const float* W_o    = (const float*)d_in[8];
    const float* b_o    = (const float*)d_in[9];
    float* out = (float*)d_out;

    float *pQ, *pK, *pV, *pY;
    cudaGetSymbolAddress((void**)&pQ, g_Q);
    cudaGetSymbolAddress((void**)&pK, g_K);
    cudaGetSymbolAddress((void**)&pV, g_V);
    cudaGetSymbolAddress((void**)&pY, g_Y);

    __nv_bfloat16 *a1h, *a1l, *a2h, *a2l;
    __nv_bfloat16 *wqh, *wql, *wkh, *wkl, *wvh, *wvl, *woh, *wol;
    __nv_bfloat16 *qsh, *qsl, *ksh, *ksl, *vth, *vtl;
    cudaGetSymbolAddress((void**)&a1h, g_a1_hi);
    cudaGetSymbolAddress((void**)&a1l, g_a1_lo);
    cudaGetSymbolAddress((void**)&a2h, g_a2_hi);
    cudaGetSymbolAddress((void**)&a2l, g_a2_lo);
    cudaGetSymbolAddress((void**)&wqh, g_wq_hi);
    cudaGetSymbolAddress((void**)&wql, g_wq_lo);
    cudaGetSymbolAddress((void**)&wkh, g_wk_hi);
    cudaGetSymbolAddress((void**)&wkl, g_wk_lo);
    cudaGetSymbolAddress((void**)&wvh, g_wv_hi);
    cudaGetSymbolAddress((void**)&wvl, g_wv_lo);
    cudaGetSymbolAddress((void**)&woh, g_wo_hi);
    cudaGetSymbolAddress((void**)&wol, g_wo_lo);
    cudaGetSymbolAddress((void**)&qsh, g_qs_hi);
    cudaGetSymbolAddress((void**)&qsl, g_qs_lo);
    cudaGetSymbolAddress((void**)&ksh, g_ks_hi);
    cudaGetSymbolAddress((void**)&ksl, g_ks_lo);
    cudaGetSymbolAddress((void**)&vth, g_vt_hi);
    cudaGetSymbolAddress((void**)&vtl, g_vt_lo);

    cudaFuncSetAttribute(gemm_mma_kernel,
                         cudaFuncAttributeMaxDynamicSharedMemorySize, 65536);
    cudaFuncSetAttribute(attn_mma_kernel,
                         cudaFuncAttributeMaxDynamicSharedMemorySize, 65536);

    const int actN4 = (MROWS * DMOD) / 4;        // 1,048,576
    dim3 convGrid(actN4 / 256);
    dim3 tGrid(DMOD / 32, DMOD / 32);
    dim3 tBlk(32, 8);

    // split inputs + weights
    conv_split_kernel<<<convGrid, 256>>>(tgt,    a1h, a1l, actN4);
    conv_split_kernel<<<convGrid, 256>>>(memory, a2h, a2l, actN4);
    convT_split_kernel<<<tGrid, tBlk>>>(W_q, wqh, wql);
    convT_split_kernel<<<tGrid, tBlk>>>(W_k, wkh, wkl);
    convT_split_kernel<<<tGrid, tBlk>>>(W_v, wvh, wvl);
    convT_split_kernel<<<tGrid, tBlk>>>(W_o, woh, wol);

    // projections (tensor cores via mma.sync)
    dim3 ggrid(DMOD / 128, MROWS / 128);         // (8, 32)
    gemm_mma_kernel<<<ggrid, 256, 65536>>>(a1h, a1l, wqh, wql, b_q, pQ);
    gemm_mma_kernel<<<ggrid, 256, 65536>>>(a2h, a2l, wkh, wkl, b_k, pK);
    gemm_mma_kernel<<<ggrid, 256, 65536>>>(a2h, a2l, wvh, wvl, b_v, pV);

    // relayout for attention
    qk_permute_split_kernel<<<convGrid, 256>>>(pQ, qsh, qsl, 0.125f);
    qk_permute_split_kernel<<<convGrid, 256>>>(pK, ksh, ksl, 1.0f);
    dim3 vtGrid(TENC / 32, DH / 32, BB * NH);    // (64, 2, 32)
    v_transpose_split_kernel<<<vtGrid, tBlk>>>(pV, vth, vtl);

    // attention (tensor cores)
    dim3 agrid(TDEC / 128, NH, BB);              // (16, 16, 2)
    attn_mma_kernel<<<agrid, 256, 65536>>>(qsh, qsl, ksh, ksl, vth, vtl);

    // output projection
    conv_split_kernel<<<convGrid, 256>>>(pY, a1h, a1l, actN4);
    gemm_mma_kernel<<<ggrid, 256, 65536>>>(a1h, a1l, woh, wol, b_o, out);
}

// round 5
// speedup vs baseline: 4.2460x; 1.4724x over previous
#include <cuda_runtime.h>
#include <cuda_fp16.h>
#include <cstdint>

#define BB    2
#define TDEC  2048
#define TENC  2048
#define DMOD  1024
#define NH    16
#define DH    64
#define MROWS (BB * TDEC)   // 4096

// ---------------------------------------------------------------------------
// Scratch (allocation-free rule: __device__ globals)
// ---------------------------------------------------------------------------
__device__ float g_Q[(size_t)MROWS * DMOD];
__device__ float g_K[(size_t)MROWS * DMOD];
__device__ float g_V[(size_t)MROWS * DMOD];
__device__ float g_Y[(size_t)MROWS * DMOD];

// fp16 splits: activations get hi/lo, weights single fp16 (transposed)
__device__ __half g_a1_hi[(size_t)MROWS * DMOD];
__device__ __half g_a1_lo[(size_t)MROWS * DMOD];
__device__ __half g_a2_hi[(size_t)MROWS * DMOD];
__device__ __half g_a2_lo[(size_t)MROWS * DMOD];
__device__ __half g_wq[(size_t)DMOD * DMOD];
__device__ __half g_wk[(size_t)DMOD * DMOD];
__device__ __half g_wv[(size_t)DMOD * DMOD];
__device__ __half g_wo[(size_t)DMOD * DMOD];

// attention-layout: Q [b][h][tok][d] hi/lo, K [b][h][tok][d], Vt [b][h][d][tok]
__device__ __half g_qs_hi[(size_t)MROWS * DMOD];
__device__ __half g_qs_lo[(size_t)MROWS * DMOD];
__device__ __half g_ks[(size_t)MROWS * DMOD];
__device__ __half g_vt[(size_t)MROWS * DMOD];

// ---------------------------------------------------------------------------
// Helpers (sm_80-compatible PTX only — harness targets compute_103)
// ---------------------------------------------------------------------------
__device__ __forceinline__ uint32_t smem_u32(const void* p) {
    uint32_t r;
    asm("{ .reg .u64 t; cvta.to.shared.u64 t, %1; cvt.u32.u64 %0, t; }"
        : "=r"(r) : "l"(p));
    return r;
}

__device__ __forceinline__ void cp16(uint32_t dst, const void* src) {
    asm volatile("cp.async.cg.shared.global [%0], [%1], 16;\n"
                 :: "r"(dst), "l"(src));
}
#define CP_COMMIT() asm volatile("cp.async.commit_group;\n" ::: "memory")
#define CP_WAIT0()  asm volatile("cp.async.wait_group 0;\n" ::: "memory")

// D += A(16x16 f16, row) * B(16x8 f16, col), fp32 accum
__device__ __forceinline__ void mma_f16(float* d, const uint32_t* a, const uint32_t* b) {
    asm volatile(
        "mma.sync.aligned.m16n8k16.row.col.f32.f16.f16.f32 "
        "{%0,%1,%2,%3}, {%4,%5,%6,%7}, {%8,%9}, {%0,%1,%2,%3};\n"
        : "+f"(d[0]), "+f"(d[1]), "+f"(d[2]), "+f"(d[3])
        : "r"(a[0]), "r"(a[1]), "r"(a[2]), "r"(a[3]),
          "r"(b[0]), "r"(b[1]));
}

__device__ __forceinline__ void split_pack2h(float a, float b, uint32_t& hi, uint32_t& lo) {
    __half ha = __float2half_rn(a), hb = __float2half_rn(b);
    float la = a - __half2float(ha);
    float lb = b - __half2float(hb);
    __half2 H = __halves2half2(ha, hb);
    __half2 L = __halves2half2(__float2half_rn(la), __float2half_rn(lb));
    hi = *reinterpret_cast<uint32_t*>(&H);
    lo = *reinterpret_cast<uint32_t*>(&L);
}

// ---------------------------------------------------------------------------
// fp32 -> fp16 hi/lo (row-major, same layout)
// ---------------------------------------------------------------------------
__global__ __launch_bounds__(256) void conv_split_kernel(
    const float* __restrict__ x, __half* __restrict__ hi,
    __half* __restrict__ lo, int n4)
{
    int i = blockIdx.x * blockDim.x + threadIdx.x;
    if (i >= n4) return;
    float4 v = ((const float4*)x)[i];
    __half h0 = __float2half_rn(v.x);
    __half h1 = __float2half_rn(v.y);
    __half h2 = __float2half_rn(v.z);
    __half h3 = __float2half_rn(v.w);
    __half2* hp = (__half2*)(hi + (size_t)i * 4);
    __half2* lp = (__half2*)(lo + (size_t)i * 4);
    hp[0] = __halves2half2(h0, h1);
    hp[1] = __halves2half2(h2, h3);
    lp[0] = __halves2half2(__float2half_rn(v.x - __half2float(h0)),
                           __float2half_rn(v.y - __half2float(h1)));
    lp[1] = __halves2half2(__float2half_rn(v.z - __half2float(h2)),
                           __float2half_rn(v.w - __half2float(h3)));
}

// ---------------------------------------------------------------------------
// W (K x N, fp32) -> Wt (N x K, fp16) transpose
// ---------------------------------------------------------------------------
__global__ void convT_half_kernel(
    const float* __restrict__ W, __half* __restrict__ Wt)
{
    __shared__ float tile[32][33];
    int tx = threadIdx.x, ty = threadIdx.y;      // 32 x 8
    int n0 = blockIdx.x * 32, k0 = blockIdx.y * 32;
#pragma unroll
    for (int r = 0; r < 4; r++)
        tile[ty + 8 * r][tx] = W[(size_t)(k0 + ty + 8 * r) * DMOD + n0 + tx];
    __syncthreads();
#pragma unroll
    for (int r = 0; r < 4; r++)
        Wt[(size_t)(n0 + ty + 8 * r) * DMOD + k0 + tx] =
            __float2half_rn(tile[tx][ty + 8 * r]);
}

// ---------------------------------------------------------------------------
// Q: [b,tok,h*64+d] fp32 -> [b][h][tok][d] fp16 hi/lo, scaled by 1/8
// ---------------------------------------------------------------------------
__global__ __launch_bounds__(256) void q_permute_split_kernel(
    const float* __restrict__ X, __half* __restrict__ hi, __half* __restrict__ lo)
{
    int i = blockIdx.x * 256 + threadIdx.x;       // float4 granule
    int d4  = i & 15;
    int tok = (i >> 4) & 2047;
    int h   = (i >> 15) & 15;
    int b   = i >> 19;
    float4 v = *(const float4*)(X + (((size_t)b * TDEC + tok) * DMOD + h * DH + d4 * 4));
    v.x *= 0.125f; v.y *= 0.125f; v.z *= 0.125f; v.w *= 0.125f;
    __half h0 = __float2half_rn(v.x);
    __half h1 = __float2half_rn(v.y);
    __half h2 = __float2half_rn(v.z);
    __half h3 = __float2half_rn(v.w);
    size_t o = (size_t)i * 4;
    __half2* hp = (__half2*)(hi + o);
    __half2* lp = (__half2*)(lo + o);
    hp[0] = __halves2half2(h0, h1);
    hp[1] = __halves2half2(h2, h3);
    lp[0] = __halves2half2(__float2half_rn(v.x - __half2float(h0)),
                           __float2half_rn(v.y - __half2float(h1)));
    lp[1] = __halves2half2(__float2half_rn(v.z - __half2float(h2)),
                           __float2half_rn(v.w - __half2float(h3)));
}

// K: [b,tok,h*64+d] fp32 -> [b][h][tok][d] fp16 (single)
__global__ __launch_bounds__(256) void k_permute_half_kernel(
    const float* __restrict__ X, __half* __restrict__ out)
{
    int i = blockIdx.x * 256 + threadIdx.x;
    int d4  = i & 15;
    int tok = (i >> 4) & 2047;
    int h   = (i >> 15) & 15;
    int b   = i >> 19;
    float4 v = *(const float4*)(X + (((size_t)b * TDEC + tok) * DMOD + h * DH + d4 * 4));
    __half2* op = (__half2*)(out + (size_t)i * 4);
    op[0] = __halves2half2(__float2half_rn(v.x), __float2half_rn(v.y));
    op[1] = __halves2half2(__float2half_rn(v.z), __float2half_rn(v.w));
}

// V: [b,tok,h*64+d] fp32 -> Vt [b][h][d][tok] fp16 (single)
__global__ void v_transpose_half_kernel(
    const float* __restrict__ V, __half* __restrict__ Vt)
{
    __shared__ float tile[32][33];
    int tx = threadIdx.x, ty = threadIdx.y;      // 32 x 8
    int t0 = blockIdx.x * 32;
    int d0 = blockIdx.y * 32;
    int bh = blockIdx.z;
    int b = bh >> 4, h = bh & 15;
#pragma unroll
    for (int r = 0; r < 4; r++)
        tile[ty + 8 * r][tx] =
            V[((size_t)b * TENC + t0 + ty + 8 * r) * DMOD + h * DH + d0 + tx];
    __syncthreads();
#pragma unroll
    for (int r = 0; r < 4; r++)
        Vt[((size_t)bh * DH + d0 + ty + 8 * r) * TENC + t0 + tx] =
            __float2half_rn(tile[tx][ty + 8 * r]);
}

// ---------------------------------------------------------------------------
// fp16 2-term mma.sync GEMM: C[M,1024] = A[M,1024] @ Wt^T + bias
// CTA 128x128, 8 warps (warp tile 64x32), K chunk 32, cp.async 2-stage.
// smem: 2 stages x 3 tiles (Ah, Al, B) x 2048 words, XOR swizzle.
// ---------------------------------------------------------------------------
#define SWZ(row, ch) (((ch) ^ (((row) >> 1) & 3)) << 2)

__global__ __launch_bounds__(256) void gemm_mma_kernel(
    const __half* __restrict__ Ahi, const __half* __restrict__ Alo,
    const __half* __restrict__ B,
    const float* __restrict__ bias, float* __restrict__ C)
{
    extern __shared__ uint32_t sw[];
    uint32_t sbase = smem_u32(sw);
    const int tid = threadIdx.x;
    const int w = tid >> 5, lane = tid & 31, g = lane >> 2, t = lane & 3;
    const int wm = (w >> 2) * 64, wn = (w & 3) * 32;
    const int brow = blockIdx.y * 128, bcol = blockIdx.x * 128;

    float acc[4][4][4];
#pragma unroll
    for (int a = 0; a < 4; a++)
#pragma unroll
        for (int bq = 0; bq < 4; bq++)
#pragma unroll
            for (int cc = 0; cc < 4; cc++) acc[a][bq][cc] = 0.f;

    auto load_chunk = [&](int c, int bf) {
        const int k0 = c * 32;
#pragma unroll
        for (int i = 0; i < 6; i++) {
            int task = tid + i * 256;            // 0..1535
            int tile = task >> 9;                // 0..2, constant per i-pair
            int r = (task >> 2) & 127;
            int ch = task & 3;
            const __half* src;
            if (tile == 0)      src = Ahi + (size_t)(brow + r) * DMOD + k0 + ch * 8;
            else if (tile == 1) src = Alo + (size_t)(brow + r) * DMOD + k0 + ch * 8;
            else                src = B   + (size_t)(bcol + r) * DMOD + k0 + ch * 8;
            uint32_t dst = sbase + (((bf * 3 + tile) * 2048) + r * 16 + SWZ(r, ch)) * 4;
            cp16(dst, src);
        }
        CP_COMMIT();
    };

    load_chunk(0, 0);
    for (int c = 0; c < 32; c++) {
        CP_WAIT0();
        __syncthreads();
        if (c + 1 < 32) load_chunk(c + 1, (c + 1) & 1);
        const uint32_t tb = (uint32_t)(c & 1) * 3 * 2048;

#pragma unroll
        for (int ks = 0; ks < 2; ks++) {
            uint32_t ah[4][4], al[4][4], b2[4][2];
#pragma unroll
            for (int mt = 0; mt < 4; mt++) {
                int r0 = wm + mt * 16 + g, r1 = r0 + 8;
                ah[mt][0] = sw[tb + 0 * 2048 + r0 * 16 + SWZ(r0, ks * 2)     + t];
                ah[mt][1] = sw[tb + 0 * 2048 + r1 * 16 + SWZ(r1, ks * 2)     + t];
                ah[mt][2] = sw[tb + 0 * 2048 + r0 * 16 + SWZ(r0, ks * 2 + 1) + t];
                ah[mt][3] = sw[tb + 0 * 2048 + r1 * 16 + SWZ(r1, ks * 2 + 1) + t];
                al[mt][0] = sw[tb + 1 * 2048 + r0 * 16 + SWZ(r0, ks * 2)     + t];
                al[mt][1] = sw[tb + 1 * 2048 + r1 * 16 + SWZ(r1, ks * 2)     + t];
                al[mt][2] = sw[tb + 1 * 2048 + r0 * 16 + SWZ(r0, ks * 2 + 1) + t];
                al[mt][3] = sw[tb + 1 * 2048 + r1 * 16 + SWZ(r1, ks * 2 + 1) + t];
            }
#pragma unroll
            for (int nt = 0; nt < 4; nt++) {
                int r0 = wn + nt * 8 + g;
                b2[nt][0] = sw[tb + 2 * 2048 + r0 * 16 + SWZ(r0, ks * 2)     + t];
                b2[nt][1] = sw[tb + 2 * 2048 + r0 * 16 + SWZ(r0, ks * 2 + 1) + t];
            }
#pragma unroll
            for (int mt = 0; mt < 4; mt++)
#pragma unroll
                for (int nt = 0; nt < 4; nt++) {
                    mma_f16(acc[mt][nt], ah[mt], b2[nt]);
                    mma_f16(acc[mt][nt], al[mt], b2[nt]);
                }
        }
    }

#pragma unroll
    for (int mt = 0; mt < 4; mt++)
#pragma unroll
        for (int nt = 0; nt < 4; nt++) {
            int r0 = brow + wm + mt * 16 + g;
            int col = bcol + wn + nt * 8 + 2 * t;
            float b0 = bias[col], b1 = bias[col + 1];
            float2 v0 = make_float2(acc[mt][nt][0] + b0, acc[mt][nt][1] + b1);
            float2 v1 = make_float2(acc[mt][nt][2] + b0, acc[mt][nt][3] + b1);
            *(float2*)&C[(size_t)r0 * DMOD + col] = v0;
            *(float2*)&C[(size_t)(r0 + 8) * DMOD + col] = v1;
        }
}

// ---------------------------------------------------------------------------
// Flash attention on mma.sync (fp16 2-term for QK and PV).
// Grid (TDEC/128, NH, BB); 8 warps; warp = 16 Q rows. K-tiles of 64 keys.
// smem: 2 stages x 2 tiles (K, Vt) x 2048 words, XOR swizzle.
// ---------------------------------------------------------------------------
#define ASWZ(row, ch) (((ch) ^ ((row) & 7)) << 2)

__global__ __launch_bounds__(256) void attn_mma_kernel(
    const __half* __restrict__ Qh, const __half* __restrict__ Ql,
    const __half* __restrict__ Kk, const __half* __restrict__ Vt)
{
    extern __shared__ uint32_t sw[];
    uint32_t sbase = smem_u32(sw);
    const int tid = threadIdx.x;
    const int w = tid >> 5, lane = tid & 31, g = lane >> 2, t = lane & 3;
    const int qb = blockIdx.x * 128;
    const int h = blockIdx.y, b = blockIdx.z;
    const size_t bh = (size_t)b * NH + h;

    // Q fragments (pre-scaled by 1/8), rows w*16 .. w*16+15
    uint32_t qh4[4][4], ql4[4][4];
    {
        const uint32_t* qH = (const uint32_t*)(Qh + (bh * TDEC + qb + w * 16) * DH);
        const uint32_t* qL = (const uint32_t*)(Ql + (bh * TDEC + qb + w * 16) * DH);
#pragma unroll
        for (int kt = 0; kt < 4; kt++) {
            qh4[kt][0] = qH[g * 32 + kt * 8 + t];
            qh4[kt][1] = qH[(g + 8) * 32 + kt * 8 + t];
            qh4[kt][2] = qH[g * 32 + kt * 8 + t + 4];
            qh4[kt][3] = qH[(g + 8) * 32 + kt * 8 + t + 4];
            ql4[kt][0] = qL[g * 32 + kt * 8 + t];
            ql4[kt][1] = qL[(g + 8) * 32 + kt * 8 + t];
            ql4[kt][2] = qL[g * 32 + kt * 8 + t + 4];
            ql4[kt][3] = qL[(g + 8) * 32 + kt * 8 + t + 4];
        }
    }

    float of[8][4];
#pragma unroll
    for (int nt = 0; nt < 8; nt++)
#pragma unroll
        for (int j = 0; j < 4; j++) of[nt][j] = 0.f;
    float m0 = -1e30f, m1 = -1e30f, l0 = 0.f, l1 = 0.f;

    auto load_kt = [&](int kt, int bf) {
#pragma unroll
        for (int i = 0; i < 4; i++) {
            int task = tid + i * 256;            // 0..1023
            int tile = task >> 9;                // 0 or 1
            int r = (task >> 3) & 63;
            int ch = task & 7;
            const __half* src;
            if (tile == 0) src = Kk + (bh * TENC + kt * 64 + r) * DH + ch * 8;
            else           src = Vt + (bh * DH + r) * TENC + kt * 64 + ch * 8;
            uint32_t dst = sbase + (((bf * 2 + tile) * 2048) + r * 32 + ASWZ(r, ch)) * 4;
            cp16(dst, src);
        }
        CP_COMMIT();
    };

    load_kt(0, 0);
    for (int kt = 0; kt < 32; kt++) {
        CP_WAIT0();
        __syncthreads();
        if (kt + 1 < 32) load_kt(kt + 1, (kt + 1) & 1);
        const uint32_t tb = (uint32_t)(kt & 1) * 2 * 2048;

        // ---- S = Q K^T (2-term: Qhi + Qlo, K single) ----
        float sf[8][4];
#pragma unroll
        for (int nt = 0; nt < 8; nt++)
#pragma unroll
            for (int j = 0; j < 4; j++) sf[nt][j] = 0.f;

#pragma unroll
        for (int dk = 0; dk < 4; dk++) {
            uint32_t kb2[8][2];
#pragma unroll
            for (int nt = 0; nt < 8; nt++) {
                int r = nt * 8 + g;
                kb2[nt][0] = sw[tb + 0 * 2048 + r * 32 + ASWZ(r, dk * 2)     + t];
                kb2[nt][1] = sw[tb + 0 * 2048 + r * 32 + ASWZ(r, dk * 2 + 1) + t];
            }
#pragma unroll
            for (int nt = 0; nt < 8; nt++) {
                mma_f16(sf[nt], qh4[dk], kb2[nt]);
                mma_f16(sf[nt], ql4[dk], kb2[nt]);
            }
        }

        // ---- online softmax (rows g and g+8) ----
        float mx0 = -1e30f, mx1 = -1e30f;
#pragma unroll
        for (int nt = 0; nt < 8; nt++) {
            mx0 = fmaxf(mx0, fmaxf(sf[nt][0], sf[nt][1]));
            mx1 = fmaxf(mx1, fmaxf(sf[nt][2], sf[nt][3]));
        }
        mx0 = fmaxf(mx0, __shfl_xor_sync(0xffffffffu, mx0, 1));
        mx0 = fmaxf(mx0, __shfl_xor_sync(0xffffffffu, mx0, 2));
        mx1 = fmaxf(mx1, __shfl_xor_sync(0xffffffffu, mx1, 1));
        mx1 = fmaxf(mx1, __shfl_xor_sync(0xffffffffu, mx1, 2));
        float mn0 = fmaxf(m0, mx0), mn1 = fmaxf(m1, mx1);
        float cr0 = __expf(m0 - mn0), cr1 = __expf(m1 - mn1);
        m0 = mn0; m1 = mn1;

        float s0 = 0.f, s1 = 0.f;
#pragma unroll
        for (int nt = 0; nt < 8; nt++) {
            sf[nt][0] = __expf(sf[nt][0] - mn0);
            sf[nt][1] = __expf(sf[nt][1] - mn0);
            sf[nt][2] = __expf(sf[nt][2] - mn1);
            sf[nt][3] = __expf(sf[nt][3] - mn1);
            s0 += sf[nt][0] + sf[nt][1];
            s1 += sf[nt][2] + sf[nt][3];
        }
        s0 += __shfl_xor_sync(0xffffffffu, s0, 1);
        s0 += __shfl_xor_sync(0xffffffffu, s0, 2);
        s1 += __shfl_xor_sync(0xffffffffu, s1, 1);
        s1 += __shfl_xor_sync(0xffffffffu, s1, 2);
        l0 = l0 * cr0 + s0;
        l1 = l1 * cr1 + s1;

#pragma unroll
        for (int nt = 0; nt < 8; nt++) {
            of[nt][0] *= cr0; of[nt][1] *= cr0;
            of[nt][2] *= cr1; of[nt][3] *= cr1;
        }

        // ---- pack P (C-frag -> A-frag, no shuffles), fp16 hi/lo split ----
        uint32_t ph[4][4], pl[4][4];
#pragma unroll
        for (int kk = 0; kk < 4; kk++) {
            split_pack2h(sf[2 * kk][0],     sf[2 * kk][1],     ph[kk][0], pl[kk][0]);
            split_pack2h(sf[2 * kk][2],     sf[2 * kk][3],     ph[kk][1], pl[kk][1]);
            split_pack2h(sf[2 * kk + 1][0], sf[2 * kk + 1][1], ph[kk][2], pl[kk][2]);
            split_pack2h(sf[2 * kk + 1][2], sf[2 * kk + 1][3], ph[kk][3], pl[kk][3]);
        }

        // ---- O += P V (2-term: Phi + Plo, V single) ----
#pragma unroll
        for (int kk = 0; kk < 4; kk++) {
            uint32_t vb2[8][2];
#pragma unroll
            for (int nt = 0; nt < 8; nt++) {
                int r = nt * 8 + g;                      // head-dim index
                vb2[nt][0] = sw[tb + 1 * 2048 + r * 32 + ASWZ(r, kk * 2)     + t];
                vb2[nt][1] = sw[tb + 1 * 2048 + r * 32 + ASWZ(r, kk * 2 + 1) + t];
            }
#pragma unroll
            for (int nt = 0; nt < 8; nt++) {
                mma_f16(of[nt], ph[kk], vb2[nt]);
                mma_f16(of[nt], pl[kk], vb2[nt]);
            }
        }
    }

    // ---- epilogue: O /= l, write [b, tok, h*64+d] ----
    float i0 = 1.f / l0, i1 = 1.f / l1;
    int r0 = qb + w * 16 + g, r1 = r0 + 8;
#pragma unroll
    for (int nt = 0; nt < 8; nt++) {
        int col = h * DH + nt * 8 + 2 * t;
        float2 v0 = make_float2(of[nt][0] * i0, of[nt][1] * i0);
        float2 v1 = make_float2(of[nt][2] * i1, of[nt][3] * i1);
        *(float2*)&g_Y[((size_t)b * TDEC + r0) * DMOD + col] = v0;
        *(float2*)&g_Y[((size_t)b * TDEC + r1) * DMOD + col] = v1;
    }
}

// ---------------------------------------------------------------------------
extern "C" void kernel_launch(void* const* d_in, const int* in_sizes, int n_in,
                              void* d_out, int out_size)
{
    (void)in_sizes; (void)n_in; (void)out_size;

    const float* tgt    = (const float*)d_in[0];
    const float* memory = (const float*)d_in[1];
    const float* W_q    = (const float*)d_in[2];
    const float* b_q    = (const float*)d_in[3];
    const float* W_k    = (const float*)d_in[4];
    const float* b_k    = (const float*)d_in[5];
    const float* W_v    = (const float*)d_in[6];
    const float* b_v    = (const float*)d_in[7];
    const float* W_o    = (const float*)d_in[8];
    const float* b_o    = (const float*)d_in[9];
    float* out = (float*)d_out;

    float *pQ, *pK, *pV, *pY;
    cudaGetSymbolAddress((void**)&pQ, g_Q);
    cudaGetSymbolAddress((void**)&pK, g_K);
    cudaGetSymbolAddress((void**)&pV, g_V);
    cudaGetSymbolAddress((void**)&pY, g_Y);

    __half *a1h, *a1l, *a2h, *a2l, *wq, *wk, *wv, *wo;
    __half *qsh, *qsl, *ks, *vt;
    cudaGetSymbolAddress((void**)&a1h, g_a1_hi);
    cudaGetSymbolAddress((void**)&a1l, g_a1_lo);
    cudaGetSymbolAddress((void**)&a2h, g_a2_hi);
    cudaGetSymbolAddress((void**)&a2l, g_a2_lo);
    cudaGetSymbolAddress((void**)&wq, g_wq);
    cudaGetSymbolAddress((void**)&wk, g_wk);
    cudaGetSymbolAddress((void**)&wv, g_wv);
    cudaGetSymbolAddress((void**)&wo, g_wo);
    cudaGetSymbolAddress((void**)&qsh, g_qs_hi);
    cudaGetSymbolAddress((void**)&qsl, g_qs_lo);
    cudaGetSymbolAddress((void**)&ks, g_ks);
    cudaGetSymbolAddress((void**)&vt, g_vt);

    cudaFuncSetAttribute(gemm_mma_kernel,
                         cudaFuncAttributeMaxDynamicSharedMemorySize, 49152);
    cudaFuncSetAttribute(attn_mma_kernel,
                         cudaFuncAttributeMaxDynamicSharedMemorySize, 32768);

    const int actN4 = (MROWS * DMOD) / 4;        // 1,048,576
    dim3 convGrid(actN4 / 256);
    dim3 tGrid(DMOD / 32, DMOD / 32);
    dim3 tBlk(32, 8);

    // split inputs + convert weights
    conv_split_kernel<<<convGrid, 256>>>(tgt,    a1h, a1l, actN4);
    conv_split_kernel<<<convGrid, 256>>>(memory, a2h, a2l, actN4);
    convT_half_kernel<<<tGrid, tBlk>>>(W_q, wq);
    convT_half_kernel<<<tGrid, tBlk>>>(W_k, wk);
    convT_half_kernel<<<tGrid, tBlk>>>(W_v, wv);
    convT_half_kernel<<<tGrid, tBlk>>>(W_o, wo);

    // projections (tensor cores via mma.sync, fp16 2-term)
    dim3 ggrid(DMOD / 128, MROWS / 128);         // (8, 32)
    gemm_mma_kernel<<<ggrid, 256, 49152>>>(a1h, a1l, wq, b_q, pQ);
    gemm_mma_kernel<<<ggrid, 256, 49152>>>(a2h, a2l, wk, b_k, pK);
    gemm_mma_kernel<<<ggrid, 256, 49152>>>(a2h, a2l, wv, b_v, pV);

    // relayout for attention
    q_permute_split_kernel<<<convGrid, 256>>>(pQ, qsh, qsl);
    k_permute_half_kernel<<<convGrid, 256>>>(pK, ks);
    dim3 vtGrid(TENC / 32, DH / 32, BB * NH);    // (64, 2, 32)
    v_transpose_half_kernel<<<vtGrid, tBlk>>>(pV, vt);

    // attention (tensor cores)
    dim3 agrid(TDEC / 128, NH, BB);              // (16, 16, 2)
    attn_mma_kernel<<<agrid, 256, 32768>>>(qsh, qsl, ks, vt);

    // output projection
    conv_split_kernel<<<convGrid, 256>>>(pY, a1h, a1l, actN4);
    gemm_mma_kernel<<<ggrid, 256, 49152>>>(a1h, a1l, wo, b_o, out);
}

// round 8
// speedup vs baseline: 4.5215x; 1.0649x over previous
#include <cuda_runtime.h>
#include <cuda_fp16.h>
#include <cstdint>

#define BB    2
#define TDEC  2048
#define TENC  2048
#define DMOD  1024
#define NH    16
#define DH    64
#define MROWS (BB * TDEC)   // 4096

// ---------------------------------------------------------------------------
// Scratch (allocation-free rule: __device__ globals)
// ---------------------------------------------------------------------------
// input splits (a1 reused as attention output / O-proj input)
__device__ __half g_a1_hi[(size_t)MROWS * DMOD];
__device__ __half g_a1_lo[(size_t)MROWS * DMOD];
__device__ __half g_a2_hi[(size_t)MROWS * DMOD];
__device__ __half g_a2_lo[(size_t)MROWS * DMOD];
// transposed fp16 weights
__device__ __half g_wq[(size_t)DMOD * DMOD];
__device__ __half g_wk[(size_t)DMOD * DMOD];
__device__ __half g_wv[(size_t)DMOD * DMOD];
__device__ __half g_wo[(size_t)DMOD * DMOD];
// attention layouts: Q hi/lo + K [bh][tok][d], V permuted [bh][tok][d], Vt [bh][d][tok]
__device__ __half g_qs_hi[(size_t)MROWS * DMOD];
__device__ __half g_qs_lo[(size_t)MROWS * DMOD];
__device__ __half g_ks[(size_t)MROWS * DMOD];
__device__ __half g_vp[(size_t)MROWS * DMOD];
__device__ __half g_vt[(size_t)MROWS * DMOD];

// ---------------------------------------------------------------------------
// Helpers (sm_80-compatible PTX only — harness targets compute_103)
// ---------------------------------------------------------------------------
__device__ __forceinline__ uint32_t smem_u32(const void* p) {
    uint32_t r;
    asm("{ .reg .u64 t; cvta.to.shared.u64 t, %1; cvt.u32.u64 %0, t; }"
        : "=r"(r) : "l"(p));
    return r;
}

__device__ __forceinline__ void cp16(uint32_t dst, const void* src) {
    asm volatile("cp.async.cg.shared.global [%0], [%1], 16;\n"
                 :: "r"(dst), "l"(src));
}
#define CP_COMMIT() asm volatile("cp.async.commit_group;\n" ::: "memory")
#define CP_WAIT0()  asm volatile("cp.async.wait_group 0;\n" ::: "memory")
#define CP_WAIT1()  asm volatile("cp.async.wait_group 1;\n" ::: "memory")

// D += A(16x16 f16, row) * B(16x8 f16, col), fp32 accum
__device__ __forceinline__ void mma_f16(float* d, const uint32_t* a, const uint32_t* b) {
    asm volatile(
        "mma.sync.aligned.m16n8k16.row.col.f32.f16.f16.f32 "
        "{%0,%1,%2,%3}, {%4,%5,%6,%7}, {%8,%9}, {%0,%1,%2,%3};\n"
        : "+f"(d[0]), "+f"(d[1]), "+f"(d[2]), "+f"(d[3])
        : "r"(a[0]), "r"(a[1]), "r"(a[2]), "r"(a[3]),
          "r"(b[0]), "r"(b[1]));
}

__device__ __forceinline__ void ldsm_x4(uint32_t* r, uint32_t addr) {
    asm volatile("ldmatrix.sync.aligned.m8n8.x4.shared.b16 {%0,%1,%2,%3}, [%4];"
                 : "=r"(r[0]), "=r"(r[1]), "=r"(r[2]), "=r"(r[3]) : "r"(addr));
}

__device__ __forceinline__ void split_pack2h(float a, float b, uint32_t& hi, uint32_t& lo) {
    __half ha = __float2half_rn(a), hb = __float2half_rn(b);
    float la = a - __half2float(ha);
    float lb = b - __half2float(hb);
    __half2 H = __halves2half2(ha, hb);
    __half2 L = __halves2half2(__float2half_rn(la), __float2half_rn(lb));
    hi = *reinterpret_cast<uint32_t*>(&H);
    lo = *reinterpret_cast<uint32_t*>(&L);
}

// ---------------------------------------------------------------------------
// fused: tgt & memory fp32 -> fp16 hi/lo (blockIdx.y selects input)
// ---------------------------------------------------------------------------
__global__ __launch_bounds__(256) void conv_split2_kernel(
    const float* __restrict__ x0, __half* __restrict__ h0, __half* __restrict__ l0,
    const float* __restrict__ x1, __half* __restrict__ h1, __half* __restrict__ l1)
{
    const float* x = blockIdx.y ? x1 : x0;
    __half* hi = blockIdx.y ? h1 : h0;
    __half* lo = blockIdx.y ? l1 : l0;
    int i = blockIdx.x * 256 + threadIdx.x;
    float4 v = ((const float4*)x)[i];
    __half a0 = __float2half_rn(v.x), a1 = __float2half_rn(v.y);
    __half a2 = __float2half_rn(v.z), a3 = __float2half_rn(v.w);
    __half2* hp = (__half2*)(hi + (size_t)i * 4);
    __half2* lp = (__half2*)(lo + (size_t)i * 4);
    hp[0] = __halves2half2(a0, a1);
    hp[1] = __halves2half2(a2, a3);
    lp[0] = __halves2half2(__float2half_rn(v.x - __half2float(a0)),
                           __float2half_rn(v.y - __half2float(a1)));
    lp[1] = __halves2half2(__float2half_rn(v.z - __half2float(a2)),
                           __float2half_rn(v.w - __half2float(a3)));
}

// ---------------------------------------------------------------------------
// fused: 4 weights (K x N fp32) -> (N x K fp16) transpose; blockIdx.z selects
// ---------------------------------------------------------------------------
__global__ void convT4_half_kernel(
    const float* __restrict__ W0, __half* __restrict__ T0,
    const float* __restrict__ W1, __half* __restrict__ T1,
    const float* __restrict__ W2, __half* __restrict__ T2,
    const float* __restrict__ W3, __half* __restrict__ T3)
{
    const float* W; __half* Wt;
    switch (blockIdx.z) {
        case 0: W = W0; Wt = T0; break;
        case 1: W = W1; Wt = T1; break;
        case 2: W = W2; Wt = T2; break;
        default: W = W3; Wt = T3; break;
    }
    __shared__ float tile[32][33];
    int tx = threadIdx.x, ty = threadIdx.y;      // 32 x 8
    int n0 = blockIdx.x * 32, k0 = blockIdx.y * 32;
#pragma unroll
    for (int r = 0; r < 4; r++)
        tile[ty + 8 * r][tx] = W[(size_t)(k0 + ty + 8 * r) * DMOD + n0 + tx];
    __syncthreads();
#pragma unroll
    for (int r = 0; r < 4; r++)
        Wt[(size_t)(n0 + ty + 8 * r) * DMOD + k0 + tx] =
            __float2half_rn(tile[tx][ty + 8 * r]);
}

// ---------------------------------------------------------------------------
// Vp [bh][tok][d] fp16 -> Vt [bh][d][tok] fp16
// ---------------------------------------------------------------------------
__global__ void v_transpose_h_kernel(
    const __half* __restrict__ vp, __half* __restrict__ vt)
{
    __shared__ __half tile[32][33];
    int tx = threadIdx.x, ty = threadIdx.y;      // 32 x 8
    int t0 = blockIdx.x * 32;
    int d0 = blockIdx.y * 32;
    int bh = blockIdx.z;
#pragma unroll
    for (int r = 0; r < 4; r++)
        tile[ty + 8 * r][tx] = vp[((size_t)bh * TENC + t0 + ty + 8 * r) * DH + d0 + tx];
    __syncthreads();
#pragma unroll
    for (int r = 0; r < 4; r++)
        vt[((size_t)bh * DH + d0 + ty + 8 * r) * TENC + t0 + tx] = tile[tx][ty + 8 * r];
}

// ---------------------------------------------------------------------------
// fp16 2-term mma.sync GEMM with fused epilogues.
// MODE 0: C = acc + bias (fp32, row-major) -> C
// MODE 1: (acc+bias)*0.125 -> split hi/lo, permuted [bh][tok][d] -> H1, H2
// MODE 2: acc+bias -> single fp16, permuted [bh][tok][d] -> H1
// CTA 128x128, 8 warps (64x32 warp tile), K chunk 32, 3-stage cp.async,
// ldmatrix fragment loads. smem: 3 stages x 3 tiles x 8KB = 72KB.
// ---------------------------------------------------------------------------
#define SWZ(row, ch) (((ch) ^ (((row) >> 1) & 3)) << 2)

template<int MODE>
__global__ __launch_bounds__(256) void gemm_mma_kernel(
    const __half* __restrict__ Ahi, const __half* __restrict__ Alo,
    const __half* __restrict__ B, const float* __restrict__ bias,
    float* __restrict__ C, __half* __restrict__ H1, __half* __restrict__ H2)
{
    extern __shared__ uint32_t sw[];
    uint32_t sbase = smem_u32(sw);
    const int tid = threadIdx.x;
    const int w = tid >> 5, lane = tid & 31, g = lane >> 2, t = lane & 3;
    const int l7 = lane & 7, sel = lane >> 3;
    const int wm = (w >> 2) * 64, wn = (w & 3) * 32;
    const int brow = blockIdx.y * 128, bcol = blockIdx.x * 128;

    float acc[4][4][4];
#pragma unroll
    for (int a = 0; a < 4; a++)
#pragma unroll
        for (int bq = 0; bq < 4; bq++)
#pragma unroll
            for (int cc = 0; cc < 4; cc++) acc[a][bq][cc] = 0.f;

    auto load_chunk = [&](int c, int st) {
        const int k0 = c * 32;
#pragma unroll
        for (int i = 0; i < 6; i++) {
            int task = tid + i * 256;            // 0..1535
            int tile = task >> 9;                // 0..2
            int r = (task >> 2) & 127;
            int ch = task & 3;
            const __half* src;
            if (tile == 0)      src = Ahi + (size_t)(brow + r) * DMOD + k0 + ch * 8;
            else if (tile == 1) src = Alo + (size_t)(brow + r) * DMOD + k0 + ch * 8;
            else                src = B   + (size_t)(bcol + r) * DMOD + k0 + ch * 8;
            uint32_t dst = sbase + (((st * 3 + tile) * 2048) + r * 16 + SWZ(r, ch)) * 4;
            cp16(dst, src);
        }
        CP_COMMIT();
    };

    load_chunk(0, 0);
    load_chunk(1, 1);
    for (int c = 0; c < 32; c++) {
        if (c == 31) { CP_WAIT0(); } else { CP_WAIT1(); }
        __syncthreads();
        if (c + 2 < 32) load_chunk(c + 2, (c + 2) % 3);
        const uint32_t tb = (uint32_t)(c % 3) * 3 * 2048;

#pragma unroll
        for (int ks = 0; ks < 2; ks++) {
            uint32_t ah[4][4], al[4][4], b2[4][2];
#pragma unroll
            for (int mt = 0; mt < 4; mt++) {
                int r = wm + mt * 16 + ((sel & 1) << 3) + l7;
                int ch = ks * 2 + (sel >> 1);
                uint32_t ad = sbase + (tb + r * 16 + SWZ(r, ch)) * 4;
                ldsm_x4(ah[mt], ad);
                ldsm_x4(al[mt], ad + 2048 * 4);
            }
#pragma unroll
            for (int np = 0; np < 2; np++) {
                int r = wn + (np * 2 + (sel >> 1)) * 8 + l7;
                int ch = ks * 2 + (sel & 1);
                uint32_t bd = sbase + (tb + 2 * 2048 + r * 16 + SWZ(r, ch)) * 4;
                uint32_t tmp[4];
                ldsm_x4(tmp, bd);
                b2[np * 2][0] = tmp[0]; b2[np * 2][1] = tmp[1];
                b2[np * 2 + 1][0] = tmp[2]; b2[np * 2 + 1][1] = tmp[3];
            }
#pragma unroll
            for (int mt = 0; mt < 4; mt++)
#pragma unroll
                for (int nt = 0; nt < 4; nt++) {
                    mma_f16(acc[mt][nt], ah[mt], b2[nt]);
                    mma_f16(acc[mt][nt], al[mt], b2[nt]);
                }
        }
    }

#pragma unroll
    for (int mt = 0; mt < 4; mt++)
#pragma unroll
        for (int nt = 0; nt < 4; nt++) {
            int r0 = brow + wm + mt * 16 + g;
            int r1 = r0 + 8;
            int col = bcol + wn + nt * 8 + 2 * t;
            float b0 = bias[col], b1 = bias[col + 1];
            float v00 = acc[mt][nt][0] + b0, v01 = acc[mt][nt][1] + b1;
            float v10 = acc[mt][nt][2] + b0, v11 = acc[mt][nt][3] + b1;
            if (MODE == 0) {
                *(float2*)&C[(size_t)r0 * DMOD + col] = make_float2(v00, v01);
                *(float2*)&C[(size_t)r1 * DMOD + col] = make_float2(v10, v11);
            } else {
                int hh = col >> 6, d = col & 63;
                size_t o0 = ((((size_t)(r0 >> 11) * NH + hh) * TDEC + (r0 & 2047)) * DH + d);
                size_t o1 = ((((size_t)(r1 >> 11) * NH + hh) * TDEC + (r1 & 2047)) * DH + d);
                if (MODE == 1) {
                    v00 *= 0.125f; v01 *= 0.125f; v10 *= 0.125f; v11 *= 0.125f;
                    uint32_t hi0, lo0, hi1, lo1;
                    split_pack2h(v00, v01, hi0, lo0);
                    split_pack2h(v10, v11, hi1, lo1);
                    *(uint32_t*)(H1 + o0) = hi0;
                    *(uint32_t*)(H2 + o0) = lo0;
                    *(uint32_t*)(H1 + o1) = hi1;
                    *(uint32_t*)(H2 + o1) = lo1;
                } else {
                    __half2 p0 = __halves2half2(__float2half_rn(v00), __float2half_rn(v01));
                    __half2 p1 = __halves2half2(__float2half_rn(v10), __float2half_rn(v11));
                    *(__half2*)(H1 + o0) = p0;
                    *(__half2*)(H1 + o1) = p1;
                }
            }
        }
}

// ---------------------------------------------------------------------------
// Flash attention on mma.sync (fp16 2-term QK and PV), ldmatrix + 3-stage.
// Grid (TDEC/128, NH, BB); 8 warps; warp = 16 Q rows. K-tiles of 64 keys.
// smem: 3 stages x 2 tiles x 8KB = 48KB. Epilogue writes split fp16 O-proj
// input (hi/lo) in [b, tok, h*64+d] layout.
// ---------------------------------------------------------------------------
#define ASWZ(row, ch) (((ch) ^ ((row) & 7)) << 2)

__global__ __launch_bounds__(256) void attn_mma_kernel(
    const __half* __restrict__ Qh, const __half* __restrict__ Ql,
    const __half* __restrict__ Kk, const __half* __restrict__ Vt,
    __half* __restrict__ Oh, __half* __restrict__ Ol)
{
    extern __shared__ uint32_t sw[];
    uint32_t sbase = smem_u32(sw);
    const int tid = threadIdx.x;
    const int w = tid >> 5, lane = tid & 31, g = lane >> 2, t = lane & 3;
    const int l7 = lane & 7, sel = lane >> 3;
    const int qb = blockIdx.x * 128;
    const int h = blockIdx.y, b = blockIdx.z;
    const size_t bh = (size_t)b * NH + h;

    // Q fragments (pre-scaled by 1/8), rows w*16 .. w*16+15
    uint32_t qh4[4][4], ql4[4][4];
    {
        const uint32_t* qH = (const uint32_t*)(Qh + (bh * TDEC + qb + w * 16) * DH);
        const uint32_t* qL = (const uint32_t*)(Ql + (bh * TDEC + qb + w * 16) * DH);
#pragma unroll
        for (int dk = 0; dk < 4; dk++) {
            qh4[dk][0] = qH[g * 32 + dk * 8 + t];
            qh4[dk][1] = qH[(g + 8) * 32 + dk * 8 + t];
            qh4[dk][2] = qH[g * 32 + dk * 8 + t + 4];
            qh4[dk][3] = qH[(g + 8) * 32 + dk * 8 + t + 4];
            ql4[dk][0] = qL[g * 32 + dk * 8 + t];
            ql4[dk][1] = qL[(g + 8) * 32 + dk * 8 + t];
            ql4[dk][2] = qL[g * 32 + dk * 8 + t + 4];
            ql4[dk][3] = qL[(g + 8) * 32 + dk * 8 + t + 4];
        }
    }

    float of[8][4];
#pragma unroll
    for (int nt = 0; nt < 8; nt++)
#pragma unroll
        for (int j = 0; j < 4; j++) of[nt][j] = 0.f;
    float m0 = -1e30f, m1 = -1e30f, l0 = 0.f, l1 = 0.f;

    auto load_kt = [&](int kt, int st) {
#pragma unroll
        for (int i = 0; i < 4; i++) {
            int task = tid + i * 256;            // 0..1023
            int tile = task >> 9;                // 0 or 1
            int r = (task >> 3) & 63;
            int ch = task & 7;
            const __half* src;
            if (tile == 0) src = Kk + (bh * TENC + kt * 64 + r) * DH + ch * 8;
            else           src = Vt + (bh * DH + r) * TENC + kt * 64 + ch * 8;
            uint32_t dst = sbase + (((st * 2 + tile) * 2048) + r * 32 + ASWZ(r, ch)) * 4;
            cp16(dst, src);
        }
        CP_COMMIT();
    };

    load_kt(0, 0);
    load_kt(1, 1);
    for (int kt = 0; kt < 32; kt++) {
        if (kt == 31) { CP_WAIT0(); } else { CP_WAIT1(); }
        __syncthreads();
        if (kt + 2 < 32) load_kt(kt + 2, (kt + 2) % 3);
        const uint32_t tb = (uint32_t)(kt % 3) * 2 * 2048;

        // ---- S = Q K^T (2-term: Qhi + Qlo, K single) ----
        float sf[8][4];
#pragma unroll
        for (int nt = 0; nt < 8; nt++)
#pragma unroll
            for (int j = 0; j < 4; j++) sf[nt][j] = 0.f;

#pragma unroll
        for (int dk = 0; dk < 4; dk++) {
            uint32_t kb2[8][2];
#pragma unroll
            for (int np = 0; np < 4; np++) {
                int r = (np * 2 + (sel >> 1)) * 8 + l7;
                int ch = dk * 2 + (sel & 1);
                uint32_t ad = sbase + (tb + r * 32 + ASWZ(r, ch)) * 4;
                uint32_t tmp[4];
                ldsm_x4(tmp, ad);
                kb2[np * 2][0] = tmp[0]; kb2[np * 2][1] = tmp[1];
                kb2[np * 2 + 1][0] = tmp[2]; kb2[np * 2 + 1][1] = tmp[3];
            }
#pragma unroll
            for (int nt = 0; nt < 8; nt++) {
                mma_f16(sf[nt], qh4[dk], kb2[nt]);
                mma_f16(sf[nt], ql4[dk], kb2[nt]);
            }
        }

        // ---- online softmax (rows g and g+8) ----
        float mx0 = -1e30f, mx1 = -1e30f;
#pragma unroll
        for (int nt = 0; nt < 8; nt++) {
            mx0 = fmaxf(mx0, fmaxf(sf[nt][0], sf[nt][1]));
            mx1 = fmaxf(mx1, fmaxf(sf[nt][2], sf[nt][3]));
        }
        mx0 = fmaxf(mx0, __shfl_xor_sync(0xffffffffu, mx0, 1));
        mx0 = fmaxf(mx0, __shfl_xor_sync(0xffffffffu, mx0, 2));
        mx1 = fmaxf(mx1, __shfl_xor_sync(0xffffffffu, mx1, 1));
        mx1 = fmaxf(mx1, __shfl_xor_sync(0xffffffffu, mx1, 2));
        float mn0 = fmaxf(m0, mx0), mn1 = fmaxf(m1, mx1);
        float cr0 = __expf(m0 - mn0), cr1 = __expf(m1 - mn1);
        m0 = mn0; m1 = mn1;

        float s0 = 0.f, s1 = 0.f;
#pragma unroll
        for (int nt = 0; nt < 8; nt++) {
            sf[nt][0] = __expf(sf[nt][0] - mn0);
            sf[nt][1] = __expf(sf[nt][1] - mn0);
            sf[nt][2] = __expf(sf[nt][2] - mn1);
            sf[nt][3] = __expf(sf[nt][3] - mn1);
            s0 += sf[nt][0] + sf[nt][1];
            s1 += sf[nt][2] + sf[nt][3];
        }
        s0 += __shfl_xor_sync(0xffffffffu, s0, 1);
        s0 += __shfl_xor_sync(0xffffffffu, s0, 2);
        s1 += __shfl_xor_sync(0xffffffffu, s1, 1);
        s1 += __shfl_xor_sync(0xffffffffu, s1, 2);
        l0 = l0 * cr0 + s0;
        l1 = l1 * cr1 + s1;

#pragma unroll
        for (int nt = 0; nt < 8; nt++) {
            of[nt][0] *= cr0; of[nt][1] *= cr0;
            of[nt][2] *= cr1; of[nt][3] *= cr1;
        }

        // ---- pack P (C-frag -> A-frag identity), fp16 hi/lo split ----
        uint32_t ph[4][4], pl[4][4];
#pragma unroll
        for (int kk = 0; kk < 4; kk++) {
            split_pack2h(sf[2 * kk][0],     sf[2 * kk][1],     ph[kk][0], pl[kk][0]);
            split_pack2h(sf[2 * kk][2],     sf[2 * kk][3],     ph[kk][1], pl[kk][1]);
            split_pack2h(sf[2 * kk + 1][0], sf[2 * kk + 1][1], ph[kk][2], pl[kk][2]);
            split_pack2h(sf[2 * kk + 1][2], sf[2 * kk + 1][3], ph[kk][3], pl[kk][3]);
        }

        // ---- O += P V (2-term: Phi + Plo, V single) ----
#pragma unroll
        for (int kk = 0; kk < 4; kk++) {
            uint32_t vb2[8][2];
#pragma unroll
            for (int np = 0; np < 4; np++) {
                int r = (np * 2 + (sel >> 1)) * 8 + l7;
                int ch = kk * 2 + (sel & 1);
                uint32_t ad = sbase + (tb + 2048 + r * 32 + ASWZ(r, ch)) * 4;
                uint32_t tmp[4];
                ldsm_x4(tmp, ad);
                vb2[np * 2][0] = tmp[0]; vb2[np * 2][1] = tmp[1];
                vb2[np * 2 + 1][0] = tmp[2]; vb2[np * 2 + 1][1] = tmp[3];
            }
#pragma unroll
            for (int nt = 0; nt < 8; nt++) {
                mma_f16(of[nt], ph[kk], vb2[nt]);
                mma_f16(of[nt], pl[kk], vb2[nt]);
            }
        }
    }

    // ---- epilogue: O /= l, split fp16 write to [b, tok, h*64+d] ----
    float i0 = 1.f / l0, i1 = 1.f / l1;
    int r0 = qb + w * 16 + g, r1 = r0 + 8;
#pragma unroll
    for (int nt = 0; nt < 8; nt++) {
        int col = h * DH + nt * 8 + 2 * t;
        size_t o0 = ((size_t)b * TDEC + r0) * DMOD + col;
        size_t o1 = ((size_t)b * TDEC + r1) * DMOD + col;
        uint32_t hi0, lo0, hi1, lo1;
        split_pack2h(of[nt][0] * i0, of[nt][1] * i0, hi0, lo0);
        split_pack2h(of[nt][2] * i1, of[nt][3] * i1, hi1, lo1);
        *(uint32_t*)(Oh + o0) = hi0;
        *(uint32_t*)(Ol + o0) = lo0;
        *(uint32_t*)(Oh + o1) = hi1;
        *(uint32_t*)(Ol + o1) = lo1;
    }
}

// ---------------------------------------------------------------------------
extern "C" void kernel_launch(void* const* d_in, const int* in_sizes, int n_in,
                              void* d_out, int out_size)
{
    (void)in_sizes; (void)n_in; (void)out_size;

    const float* tgt    = (const float*)d_in[0];
    const float* memory = (const float*)d_in[1];
    const float* W_q    = (const float*)d_in[2];
    const float* b_q    = (const float*)d_in[3];
    const float* W_k    = (const float*)d_in[4];
    const float* b_k    = (const float*)d_in[5];
    const float* W_v    = (const float*)d_in[6];
    const float* b_v    = (const float*)d_in[7];
    const float* W_o    = (const float*)d_in[8];
    const float* b_o    = (const float*)d_in[9];
    float* out = (float*)d_out;

    __half *a1h, *a1l, *a2h, *a2l, *wq, *wk, *wv, *wo;
    __half *qsh, *qsl, *ks, *vp, *vt;
    cudaGetSymbolAddress((void**)&a1h, g_a1_hi);
    cudaGetSymbolAddress((void**)&a1l, g_a1_lo);
    cudaGetSymbolAddress((void**)&a2h, g_a2_hi);
    cudaGetSymbolAddress((void**)&a2l, g_a2_lo);
    cudaGetSymbolAddress((void**)&wq, g_wq);
    cudaGetSymbolAddress((void**)&wk, g_wk);
    cudaGetSymbolAddress((void**)&wv, g_wv);
    cudaGetSymbolAddress((void**)&wo, g_wo);
    cudaGetSymbolAddress((void**)&qsh, g_qs_hi);
    cudaGetSymbolAddress((void**)&qsl, g_qs_lo);
    cudaGetSymbolAddress((void**)&ks, g_ks);
    cudaGetSymbolAddress((void**)&vp, g_vp);
    cudaGetSymbolAddress((void**)&vt, g_vt);

    const int GEMM_SMEM = 3 * 3 * 2048 * 4;      // 73728
    const int ATTN_SMEM = 3 * 2 * 2048 * 4;      // 49152
    cudaFuncSetAttribute(gemm_mma_kernel<0>,
                         cudaFuncAttributeMaxDynamicSharedMemorySize, GEMM_SMEM);
    cudaFuncSetAttribute(gemm_mma_kernel<1>,
                         cudaFuncAttributeMaxDynamicSharedMemorySize, GEMM_SMEM);
    cudaFuncSetAttribute(gemm_mma_kernel<2>,
                         cudaFuncAttributeMaxDynamicSharedMemorySize, GEMM_SMEM);
    cudaFuncSetAttribute(attn_mma_kernel,
                         cudaFuncAttributeMaxDynamicSharedMemorySize, ATTN_SMEM);

    // split inputs (fused), transpose weights (fused)
    dim3 csGrid((MROWS * DMOD / 4) / 256, 2);
    conv_split2_kernel<<<csGrid, 256>>>(tgt, a1h, a1l, memory, a2h, a2l);
    dim3 tGrid(DMOD / 32, DMOD / 32, 4);
    dim3 tBlk(32, 8);
    convT4_half_kernel<<<tGrid, tBlk>>>(W_q, wq, W_k, wk, W_v, wv, W_o, wo);

    // projections with fused permute/split epilogues
    dim3 ggrid(DMOD / 128, MROWS / 128);         // (8, 32)
    gemm_mma_kernel<1><<<ggrid, 256, GEMM_SMEM>>>(a1h, a1l, wq, b_q, nullptr, qsh, qsl);
    gemm_mma_kernel<2><<<ggrid, 256, GEMM_SMEM>>>(a2h, a2l, wk, b_k, nullptr, ks, nullptr);
    gemm_mma_kernel<2><<<ggrid, 256, GEMM_SMEM>>>(a2h, a2l, wv, b_v, nullptr, vp, nullptr);

    // V transpose (fp16 -> fp16)
    dim3 vtGrid(TENC / 32, DH / 32, BB * NH);    // (64, 2, 32)
    v_transpose_h_kernel<<<vtGrid, tBlk>>>(vp, vt);

    // attention (epilogue emits split O-proj input)
    dim3 agrid(TDEC / 128, NH, BB);              // (16, 16, 2)
    attn_mma_kernel<<<agrid, 256, ATTN_SMEM>>>(qsh, qsl, ks, vt, a1h, a1l);

    // output projection
    gemm_mma_kernel<0><<<ggrid, 256, GEMM_SMEM>>>(a1h, a1l, wo, b_o, out, nullptr, nullptr);
}